// round 11
// baseline (speedup 1.0000x reference)
#include <cuda_runtime.h>
#include <cuda_bf16.h>

#define TT 256
#define SIGMA_INV (1.0f / 100.0f)
#define BLOCKS 304
#define THREADS 256
#define WPB 8                  // warps per block
#define R 4                    // rows per warp (interleaved)

// Scratch: device globals (allocation-free rule). Zero at module load; the
// LAST block re-zeros after consuming, so every graph replay sees clean state.
__device__ float        gS[TT];   // S[t] = sum_j ev_j [y_j > t] exp(F1[j,t]/s)
__device__ float        gH[TT];   // H[t] = sum_{i: y_i = t} ev_i exp(-A_i/s)
__device__ double       gL1;
__device__ unsigned int gCount;

// exp(x) for |x| <= 0.009 : cubic Taylor, rel err < 3e-10
__device__ __forceinline__ float exp_small(float x) {
    return fmaf(x, fmaf(x, fmaf(x, 0.16666667f, 0.5f), 1.0f), 1.0f);
}

__global__ void __launch_bounds__(THREADS, 2)
surv_fused(const float* __restrict__ yp,
           const void*  __restrict__ yv,
           const float* __restrict__ status,
           int N,
           float* __restrict__ out) {
    const int t    = threadIdx.x;
    const int lane = t & 31;
    const int w    = t >> 5;
    const int gw   = blockIdx.x * WPB + w;
    const int W    = gridDim.x * WPB;      // 2432 warps -> 4 rows each
    const int* y32 = (const int*)yv;

    // ---- issue ALL independent global loads up front (max MLP) ----
    const int det = (2 * lane + 1 < N) ? y32[2 * lane + 1] : 0;

    int  jr[R]; bool val[R];
    float4 d0[R], d1[R];
    #pragma unroll
    for (int r = 0; r < R; r++) {
        jr[r] = gw + r * W;
        val[r] = (jr[r] < N);
        if (val[r]) {
            const float* p = yp + (size_t)jr[r] * TT + lane * 8;
            d0[r] = *(const float4*)(p);
            d1[r] = *(const float4*)(p + 4);
        }
    }

    // speculative metadata (lane 0): int32 candidate (word j) and int64
    // candidate (word 2j, when 2j<N — in-bounds under both interpretations)
    int c32[R] = {0}, c64[R] = {0};
    float cst[R] = {0.0f, 0.0f, 0.0f, 0.0f};
    if (lane == 0) {
        #pragma unroll
        for (int r = 0; r < R; r++) if (val[r]) {
            c32[r] = y32[jr[r]];
            if (2 * jr[r] < N) c64[r] = y32[2 * jr[r]];
            cst[r] = status[jr[r]];
        }
    }

    // width detect (int64 LE: odd 32-bit words all zero since 0 <= y < 256)
    const bool is64 = (__ballot_sync(0xffffffffu, det != 0) == 0u);

    int pk0 = 0, pk1 = 0;
    if (lane == 0) {
        int yy[R];
        #pragma unroll
        for (int r = 0; r < R; r++)
            yy[r] = val[r]
                  ? (is64 ? ((2 * jr[r] < N) ? c64[r] : y32[2 * jr[r]]) : c32[r])
                  : 0;
        pk0 = yy[0] | ((cst[0] > 0.5f) ? 256 : 0)
            | (yy[1] << 16) | ((cst[1] > 0.5f) ? (1 << 24) : 0);
        pk1 = yy[2] | ((cst[2] > 0.5f) ? 256 : 0)
            | (yy[3] << 16) | ((cst[3] > 0.5f) ? (1 << 24) : 0);
    }

    __shared__ float sH[TT];
    __shared__ float sL1;
    sH[t] = 0.0f;
    if (t == 0) sL1 = 0.0f;
    __syncthreads();                        // visible before loop atomics

    pk0 = __shfl_sync(0xffffffffu, pk0, 0);
    pk1 = __shfl_sync(0xffffffffu, pk1, 0);
    int  ys[R] = { pk0 & 255, (pk0 >> 16) & 255, pk1 & 255, (pk1 >> 16) & 255 };
    bool ev[R] = { (pk0 & 256) != 0, (pk0 & (1 << 24)) != 0,
                   (pk1 & 256) != 0, (pk1 & (1 << 24)) != 0 };

    // ---- local inclusive prefixes (4 independent chains) ----
    float s[R][8];
    #pragma unroll
    for (int r = 0; r < R; r++) if (val[r]) {
        s[r][0] = d0[r].x;           s[r][1] = s[r][0] + d0[r].y;
        s[r][2] = s[r][1] + d0[r].z; s[r][3] = s[r][2] + d0[r].w;
        s[r][4] = s[r][3] + d1[r].x; s[r][5] = s[r][4] + d1[r].y;
        s[r][6] = s[r][5] + d1[r].z; s[r][7] = s[r][6] + d1[r].w;
    }

    // ---- 4-way interleaved warp scans (latencies overlap) ----
    float tt[R], sc[R];
    #pragma unroll
    for (int r = 0; r < R; r++) { tt[r] = val[r] ? s[r][7] : 0.0f; sc[r] = tt[r]; }
    #pragma unroll
    for (int o = 1; o < 32; o <<= 1) {
        float n[R];
        #pragma unroll
        for (int r = 0; r < R; r++) n[r] = __shfl_up_sync(0xffffffffu, sc[r], o);
        if (lane >= o) {
            #pragma unroll
            for (int r = 0; r < R; r++) sc[r] += n[r];
        }
    }
    float off[R];
    #pragma unroll
    for (int r = 0; r < R; r++) off[r] = sc[r] - tt[r];

    float acc[8];
    #pragma unroll
    for (int k = 0; k < 8; k++) acc[k] = 0.0f;
    const int base = lane * 8;

    // ---- per-row tail work ----
    #pragma unroll
    for (int r = 0; r < R; r++) if (val[r]) {
        if (lane == (ys[r] >> 3)) {          // owning lane: L1 + H, no bcast
            const int idx = ys[r] & 7;
            float A = 0.0f, p = 0.0f;
            #pragma unroll
            for (int k = 0; k < 8; k++)
                if (k == idx) { A = off[r] + s[r][k];
                                p = k ? s[r][k] - s[r][k-1] : s[r][0]; }
            atomicAdd(&sL1, ev[r] ? -__logf(p) : -__logf(1.0f - A));
            if (ev[r]) atomicAdd(&sH[ys[r]], exp_small(-A * SIGMA_INV));
        }
        if (ev[r]) {
            #pragma unroll
            for (int k = 0; k < 8; k++) {
                float e = exp_small((off[r] + s[r][k]) * SIGMA_INV);
                if (base + k < ys[r]) acc[k] += e;
            }
        }
    }

    // ---- generic fallback (not taken at N=8192 with this grid) ----
    for (int j = gw + R * W; j < N; j += W) {
        const float* p = yp + (size_t)j * TT + lane * 8;
        float4 c0 = *(const float4*)(p), c1 = *(const float4*)(p + 4);
        float q[8];
        q[0] = c0.x; q[1] = q[0]+c0.y; q[2] = q[1]+c0.z; q[3] = q[2]+c0.w;
        q[4] = q[3]+c1.x; q[5] = q[4]+c1.y; q[6] = q[5]+c1.z; q[7] = q[6]+c1.w;
        float tq = q[7], scq = tq;
        #pragma unroll
        for (int o = 1; o < 32; o <<= 1) {
            float n = __shfl_up_sync(0xffffffffu, scq, o);
            if (lane >= o) scq += n;
        }
        float offq = scq - tq;
        int pj = 0;
        if (lane == 0)
            pj = (is64 ? y32[2*j] : y32[j]) | ((status[j] > 0.5f) ? 256 : 0);
        pj = __shfl_sync(0xffffffffu, pj, 0);
        const int yj = pj & 255; const bool evj = (pj & 256) != 0;
        if (lane == (yj >> 3)) {
            const int idx = yj & 7;
            float A = 0.0f, pp = 0.0f;
            #pragma unroll
            for (int k = 0; k < 8; k++)
                if (k == idx) { A = offq + q[k]; pp = k ? q[k]-q[k-1] : q[0]; }
            atomicAdd(&sL1, evj ? -__logf(pp) : -__logf(1.0f - A));
            if (evj) atomicAdd(&sH[yj], exp_small(-A * SIGMA_INV));
        }
        if (evj) {
            #pragma unroll
            for (int k = 0; k < 8; k++) {
                float e = exp_small((offq + q[k]) * SIGMA_INV);
                if (base + k < yj) acc[k] += e;
            }
        }
    }

    // ---- epilogue: conflict-free STS.128 block reduce (16B-ALIGNED smem) ----
    __shared__ __align__(16) float sRed[WPB][TT];
    *(float4*)&sRed[w][base]     = make_float4(acc[0], acc[1], acc[2], acc[3]);
    *(float4*)&sRed[w][base + 4] = make_float4(acc[4], acc[5], acc[6], acc[7]);
    __syncthreads();
    {
        float colSum = 0.0f;
        #pragma unroll
        for (int ww = 0; ww < WPB; ww++) colSum += sRed[ww][t];
        if (colSum != 0.0f) atomicAdd(&gS[t], colSum);
        float h = sH[t];
        if (h != 0.0f) atomicAdd(&gH[t], h);
        if (t == 0) atomicAdd(&gL1, (double)sL1);
    }

    // ---- arrival counter: last block finalizes + resets ----
    __threadfence();
    __shared__ bool isLast;
    if (t == 0) {
        unsigned old = atomicAdd(&gCount, 1u);
        isLast = (old == (unsigned)(gridDim.x - 1));
    }
    __syncthreads();
    if (!isLast) return;

    // Finalize: L2 = sum_t gS[t] * gH[t]
    double d = (double)(__ldcg(&gS[t]) * __ldcg(&gH[t]));
    #pragma unroll
    for (int o = 16; o > 0; o >>= 1)
        d += __shfl_down_sync(0xffffffffu, d, o);
    __shared__ double sD[WPB];
    if (lane == 0) sD[w] = d;
    __syncthreads();
    if (t == 0) {
        double tot = 0.0;
        #pragma unroll
        for (int ww = 0; ww < WPB; ww++) tot += sD[ww];
        out[0] = (float)(gL1 + tot);
    }

    // reset for next graph replay
    __syncthreads();
    gS[t] = 0.0f;
    gH[t] = 0.0f;
    if (t == 0) { gL1 = 0.0; gCount = 0u; }
}

extern "C" void kernel_launch(void* const* d_in, const int* in_sizes, int n_in,
                              void* d_out, int out_size) {
    const float* y_pred = (const float*)d_in[0];
    const void*  y      = d_in[1];
    const float* status = (const float*)d_in[2];
    const int N = in_sizes[2];   // status length = N independent of y width
    surv_fused<<<BLOCKS, THREADS>>>(y_pred, y, status, N, (float*)d_out);
}

// round 12
// speedup vs baseline: 1.0175x; 1.0175x over previous
#include <cuda_runtime.h>
#include <cuda_bf16.h>

#define TT 256
#define SIGMA_INV (1.0f / 100.0f)
#define BLOCKS 304
#define THREADS 512
#define WPB 16                 // warps per block

// Scratch: device globals (allocation-free rule). Zero at module load; the
// LAST block re-zeros after consuming, so every graph replay sees clean state.
__device__ float        gS[TT];   // S[t] = sum_j ev_j [y_j > t] exp(F1[j,t]/s)
__device__ float        gH[TT];   // H[t] = sum_{i: y_i = t} ev_i exp(-A_i/s)
__device__ float        gL1;
__device__ unsigned int gCount;

// exp(x) for |x| <= 0.009 : cubic Taylor, rel err < 3e-10
__device__ __forceinline__ float exp_small(float x) {
    return fmaf(x, fmaf(x, fmaf(x, 0.16666667f, 0.5f), 1.0f), 1.0f);
}

// arrival with acq_rel semantics: release publishes this block's prior REDs,
// acquire (observed by the last block) orders its subsequent reads.
__device__ __forceinline__ unsigned arrive_acq_rel(unsigned int* ctr) {
    unsigned old;
    asm volatile("atom.add.acq_rel.gpu.global.u32 %0, [%1], 1;"
                 : "=r"(old) : "l"(ctr) : "memory");
    return old;
}

__global__ void __launch_bounds__(THREADS, 2)
surv_fused(const float* __restrict__ yp,
           const void*  __restrict__ yv,
           const float* __restrict__ status,
           int N,
           float* __restrict__ out) {
    const int t    = threadIdx.x;
    const int lane = t & 31;
    const int w    = t >> 5;
    const int gw   = blockIdx.x * WPB + w;
    const int W    = gridDim.x * WPB;       // 4864 total warps
    const int* y32 = (const int*)yv;

    // ---- issue ALL independent global loads up front ----
    const int det = (2 * lane + 1 < N) ? y32[2 * lane + 1] : 0;

    const int ja = gw, jb = gw + W;          // this warp's two rows
    float4 xa0, xa1, xb0, xb1;
    if (ja < N) {
        const float* r = yp + (size_t)ja * TT + lane * 8;
        xa0 = *(const float4*)(r); xa1 = *(const float4*)(r + 4);
    }
    if (jb < N) {
        const float* r = yp + (size_t)jb * TT + lane * 8;
        xb0 = *(const float4*)(r); xb1 = *(const float4*)(r + 4);
    }

    // speculative metadata: int32 candidate (word j, in-bounds always) and
    // int64 candidate (word 2j, issued when 2j < N — in-bounds under both
    // width interpretations). Status loads are width-independent.
    int y32a = 0, y32b = 0, y64a = 0, y64b = 0;
    float sta = 0.0f, stb = 0.0f;
    if (lane == 0) {
        if (ja < N) {
            y32a = y32[ja];
            if (2 * ja < N) y64a = y32[2 * ja];
            sta = status[ja];
        }
        if (jb < N) {
            y32b = y32[jb];
            if (2 * jb < N) y64b = y32[2 * jb];
            stb = status[jb];
        }
    }

    // width detect (int64 LE: odd 32-bit words all zero since 0 <= y < 256)
    const bool is64 = (__ballot_sync(0xffffffffu, det != 0) == 0u);

    int pk = 0;
    if (lane == 0) {
        if (ja < N) {
            int ya = is64 ? ((2 * ja < N) ? y64a : y32[2 * ja]) : y32a;
            pk |= ya | ((sta > 0.5f) ? 256 : 0);
        }
        if (jb < N) {
            int yb = is64 ? ((2 * jb < N) ? y64b : y32[2 * jb]) : y32b;
            pk |= (yb << 16) | ((stb > 0.5f) ? (1 << 24) : 0);
        }
    }

    __shared__ float sH[TT];
    __shared__ float sL1;
    if (t < TT) sH[t] = 0.0f;
    if (t == THREADS - 1) sL1 = 0.0f;
    __syncthreads();                          // visible before loop atomics

    pk = __shfl_sync(0xffffffffu, pk, 0);     // one broadcast for both rows
    const int  ya  = pk & 255;
    const bool eva = (pk & 256) != 0;
    const int  yb  = (pk >> 16) & 255;
    const bool evb = (pk & (1 << 24)) != 0;

    float acc[8];
    #pragma unroll
    for (int k = 0; k < 8; k++) acc[k] = 0.0f;

    // ---- local inclusive prefixes (independent chains) ----
    float sa[8], sb[8];
    if (ja < N) {
        sa[0] = xa0.x; sa[1] = sa[0] + xa0.y; sa[2] = sa[1] + xa0.z;
        sa[3] = sa[2] + xa0.w; sa[4] = sa[3] + xa1.x; sa[5] = sa[4] + xa1.y;
        sa[6] = sa[5] + xa1.z; sa[7] = sa[6] + xa1.w;
    }
    if (jb < N) {
        sb[0] = xb0.x; sb[1] = sb[0] + xb0.y; sb[2] = sb[1] + xb0.z;
        sb[3] = sb[2] + xb0.w; sb[4] = sb[3] + xb1.x; sb[5] = sb[4] + xb1.y;
        sb[6] = sb[5] + xb1.z; sb[7] = sb[6] + xb1.w;
    }

    // ---- interleaved warp scans (latencies overlap) ----
    float ta = (ja < N) ? sa[7] : 0.0f;
    float tb = (jb < N) ? sb[7] : 0.0f;
    float sca = ta, scb = tb;
    #pragma unroll
    for (int o = 1; o < 32; o <<= 1) {
        float na = __shfl_up_sync(0xffffffffu, sca, o);
        float nb = __shfl_up_sync(0xffffffffu, scb, o);
        if (lane >= o) { sca += na; scb += nb; }
    }
    const float offa = sca - ta;
    const float offb = scb - tb;
    const int base = lane * 8;

    // ---- row A ----
    if (ja < N) {
        if (lane == (ya >> 3)) {              // owning lane: L1 + H, no bcast
            const int idx = ya & 7;
            float A = 0.0f, p = 0.0f;
            #pragma unroll
            for (int k = 0; k < 8; k++)
                if (k == idx) { A = offa + sa[k]; p = k ? sa[k]-sa[k-1] : sa[0]; }
            atomicAdd(&sL1, eva ? -__logf(p) : -__logf(1.0f - A));
            if (eva) atomicAdd(&sH[ya], exp_small(-A * SIGMA_INV));
        }
        if (eva) {
            #pragma unroll
            for (int k = 0; k < 8; k++) {
                float e = exp_small((offa + sa[k]) * SIGMA_INV);
                if (base + k < ya) acc[k] += e;
            }
        }
    }

    // ---- row B ----
    if (jb < N) {
        if (lane == (yb >> 3)) {
            const int idx = yb & 7;
            float A = 0.0f, p = 0.0f;
            #pragma unroll
            for (int k = 0; k < 8; k++)
                if (k == idx) { A = offb + sb[k]; p = k ? sb[k]-sb[k-1] : sb[0]; }
            atomicAdd(&sL1, evb ? -__logf(p) : -__logf(1.0f - A));
            if (evb) atomicAdd(&sH[yb], exp_small(-A * SIGMA_INV));
        }
        if (evb) {
            #pragma unroll
            for (int k = 0; k < 8; k++) {
                float e = exp_small((offb + sb[k]) * SIGMA_INV);
                if (base + k < yb) acc[k] += e;
            }
        }
    }

    // ---- generic fallback (not taken at N=8192 with this grid) ----
    for (int j = gw + 2 * W; j < N; j += W) {
        const float* r = yp + (size_t)j * TT + lane * 8;
        float4 c0 = *(const float4*)(r), c1 = *(const float4*)(r + 4);
        float s[8];
        s[0] = c0.x; s[1] = s[0]+c0.y; s[2] = s[1]+c0.z; s[3] = s[2]+c0.w;
        s[4] = s[3]+c1.x; s[5] = s[4]+c1.y; s[6] = s[5]+c1.z; s[7] = s[6]+c1.w;
        float tt0 = s[7], sc = tt0;
        #pragma unroll
        for (int o = 1; o < 32; o <<= 1) {
            float n = __shfl_up_sync(0xffffffffu, sc, o);
            if (lane >= o) sc += n;
        }
        float off = sc - tt0;
        int pj = 0;
        if (lane == 0)
            pj = (is64 ? y32[2*j] : y32[j]) | ((status[j] > 0.5f) ? 256 : 0);
        pj = __shfl_sync(0xffffffffu, pj, 0);
        const int yj = pj & 255; const bool ev = (pj & 256) != 0;
        if (lane == (yj >> 3)) {
            const int idx = yj & 7;
            float A = 0.0f, p = 0.0f;
            #pragma unroll
            for (int k = 0; k < 8; k++)
                if (k == idx) { A = off + s[k]; p = k ? s[k]-s[k-1] : s[0]; }
            atomicAdd(&sL1, ev ? -__logf(p) : -__logf(1.0f - A));
            if (ev) atomicAdd(&sH[yj], exp_small(-A * SIGMA_INV));
        }
        if (ev) {
            #pragma unroll
            for (int k = 0; k < 8; k++) {
                float e = exp_small((off + s[k]) * SIGMA_INV);
                if (base + k < yj) acc[k] += e;
            }
        }
    }

    // ---- block-level reduce: acc -> gS, sH -> gH, sL1 -> gL1 ----
    __shared__ float sRed[WPB][TT];
    #pragma unroll
    for (int k = 0; k < 8; k++) sRed[w][base + k] = acc[k];
    __syncthreads();
    if (t < TT) {
        float colSum = 0.0f;
        #pragma unroll
        for (int ww = 0; ww < WPB; ww++) colSum += sRed[ww][t];
        if (colSum != 0.0f) atomicAdd(&gS[t], colSum);
        float h = sH[t];
        if (h != 0.0f) atomicAdd(&gH[t], h);
        if (t == 0) atomicAdd(&gL1, sL1);
    }

    // ---- arrival (acq_rel atomic, no full membar): last block finalizes ----
    __shared__ bool isLast;
    __syncthreads();                          // all block's REDs issued above
    if (t == 0)
        isLast = (arrive_acq_rel(&gCount) == (unsigned)(gridDim.x - 1));
    __syncthreads();
    if (!isLast) return;

    // Finalize: L2 = sum_t gS[t] * gH[t]  (reads ordered by acquire)
    double d = (t < TT) ? (double)(__ldcg(&gS[t]) * __ldcg(&gH[t])) : 0.0;
    #pragma unroll
    for (int o = 16; o > 0; o >>= 1)
        d += __shfl_down_sync(0xffffffffu, d, o);
    __shared__ double sD[WPB];
    if (lane == 0) sD[w] = d;
    __syncthreads();
    if (t == 0) {
        double tot = 0.0;
        #pragma unroll
        for (int ww = 0; ww < WPB; ww++) tot += sD[ww];
        out[0] = (float)((double)__ldcg(&gL1) + tot);
    }

    // reset for next graph replay
    __syncthreads();
    if (t < TT) { gS[t] = 0.0f; gH[t] = 0.0f; }
    if (t == 0) { gL1 = 0.0f; gCount = 0u; }
}

extern "C" void kernel_launch(void* const* d_in, const int* in_sizes, int n_in,
                              void* d_out, int out_size) {
    const float* y_pred = (const float*)d_in[0];
    const void*  y      = d_in[1];
    const float* status = (const float*)d_in[2];
    const int N = in_sizes[2];   // status length = N independent of y width
    surv_fused<<<BLOCKS, THREADS>>>(y_pred, y, status, N, (float*)d_out);
}